// round 16
// baseline (speedup 1.0000x reference)
#include <cuda_runtime.h>
#include <cuda_bf16.h>
#include <cstdint>

#define BSZ   2
#define NSEQ  2048
#define DMOD  1024
#define NH    16
#define DHD   64
#define MROWS (BSZ*NSEQ)
#define DD    (DMOD*DMOD)

// ---------------- device scratch (no allocations allowed) ----------------
__device__ __nv_bfloat16 g_Ah[3*MROWS*DMOD];
__device__ __nv_bfloat16 g_Al[3*MROWS*DMOD];
__device__ __nv_bfloat16 g_Wth[4*DD];
__device__ __nv_bfloat16 g_Wtl[4*DD];
__device__ __nv_bfloat16 g_Qh[MROWS*DMOD];     // [bh][n][dh], pre-scaled by 0.125*log2e
__device__ __nv_bfloat16 g_Ql[MROWS*DMOD];
__device__ __nv_bfloat16 g_Kh[MROWS*DMOD];     // [bh][n][dh]
__device__ __nv_bfloat16 g_Kl[MROWS*DMOD];
__device__ __nv_bfloat16 g_Vth[MROWS*DMOD];    // [bh][dh][n]
__device__ __nv_bfloat16 g_Vtl[MROWS*DMOD];

// ---------------- PTX helpers ----------------
__device__ __forceinline__ uint32_t smem_to_u32(const void* p) {
    uint32_t a;
    asm("{ .reg .u64 t; cvta.to.shared.u64 t, %1; cvt.u32.u64 %0, t; }" : "=r"(a) : "l"(p));
    return a;
}
__device__ __forceinline__ void cp_async16(uint32_t dst, const void* src) {
    asm volatile("cp.async.cg.shared.global [%0], [%1], 16;" :: "r"(dst), "l"(src));
}
__device__ __forceinline__ void cp_commit() {
    asm volatile("cp.async.commit_group;" ::: "memory");
}
template <int N>
__device__ __forceinline__ void cp_wait() {
    asm volatile("cp.async.wait_group %0;" :: "n"(N) : "memory");
}
__device__ __forceinline__ void ldsm_x4(uint32_t& r0, uint32_t& r1, uint32_t& r2,
                                        uint32_t& r3, uint32_t addr) {
    asm volatile("ldmatrix.sync.aligned.m8n8.x4.shared.b16 {%0,%1,%2,%3}, [%4];"
                 : "=r"(r0), "=r"(r1), "=r"(r2), "=r"(r3) : "r"(addr));
}
__device__ __forceinline__ void mma16816(float* c, uint32_t a0, uint32_t a1,
                                         uint32_t a2, uint32_t a3,
                                         uint32_t b0, uint32_t b1) {
    asm volatile("mma.sync.aligned.m16n8k16.row.col.f32.bf16.bf16.f32 "
                 "{%0,%1,%2,%3}, {%4,%5,%6,%7}, {%8,%9}, {%0,%1,%2,%3};"
                 : "+f"(c[0]), "+f"(c[1]), "+f"(c[2]), "+f"(c[3])
                 : "r"(a0), "r"(a1), "r"(a2), "r"(a3), "r"(b0), "r"(b1));
}

// exp2 via SFU: single instruction, rel err ~2^-22, ex2(-huge) = 0 exactly.
__device__ __forceinline__ float fexp2(float t) {
    float r;
    asm("ex2.approx.f32 %0, %1;" : "=f"(r) : "f"(t));
    return r;
}

__device__ __forceinline__ uint32_t pack2(float a, float b) {
    uint32_t r;
    asm("cvt.rn.bf16x2.f32 %0, %1, %2;" : "=r"(r) : "f"(b), "f"(a));
    return r;
}
__device__ __forceinline__ uint32_t res_pack(uint32_t hpk, float a, float b) {
    float ha = __int_as_float(hpk << 16);
    float hb = __int_as_float(hpk & 0xffff0000u);
    return pack2(a - ha, b - hb);
}
__device__ __forceinline__ float bf16_res(float x) {
    return x - __bfloat162float(__float2bfloat16(x));
}
#define SWZ(o) ((o) ^ (((o) >> 3) & 0x70))

// ---------------- prep kernels ----------------
__global__ __launch_bounds__(256)
void asplit_all(const float4* __restrict__ X0, const float4* __restrict__ X1,
                const float4* __restrict__ X2, uint2* __restrict__ Xh,
                uint2* __restrict__ Xl, int n4)
{
    const int z = blockIdx.z;
    const float4* X = (z == 0) ? X0 : ((z == 1) ? X1 : X2);
    int i = blockIdx.x*256 + threadIdx.x;
    if (i >= n4) return;
    float4 v = X[i];
    uint2 uh, ul;
    uh.x = pack2(v.x, v.y); uh.y = pack2(v.z, v.w);
    ul.x = res_pack(uh.x, v.x, v.y); ul.y = res_pack(uh.y, v.z, v.w);
    Xh[(size_t)z*n4 + i] = uh; Xl[(size_t)z*n4 + i] = ul;
}

__global__ __launch_bounds__(256)
void wsplit_all(const float* __restrict__ W0, const float* __restrict__ W1,
                const float* __restrict__ W2, const float* __restrict__ W3,
                __nv_bfloat16* __restrict__ Wth, __nv_bfloat16* __restrict__ Wtl)
{
    __shared__ float ts[32][33];
    const int z = blockIdx.z;
    const float* W = (z == 0) ? W0 : ((z == 1) ? W1 : ((z == 2) ? W2 : W3));
    __nv_bfloat16* th = Wth + (size_t)z*DD;
    __nv_bfloat16* tl = Wtl + (size_t)z*DD;
    const int tx = threadIdx.x, ty = threadIdx.y;
    const int gx = blockIdx.x*32, gy = blockIdx.y*32;
    #pragma unroll
    for (int i = ty; i < 32; i += 8)
        ts[i][tx] = W[(size_t)(gy+i)*DMOD + gx + tx];
    __syncthreads();
    #pragma unroll
    for (int i = ty; i < 32; i += 8) {
        float v = ts[tx][i];
        __nv_bfloat16 h = __float2bfloat16(v);
        th[(size_t)(gx+i)*DMOD + gy + tx] = h;
        tl[(size_t)(gx+i)*DMOD + gy + tx] = __float2bfloat16(v - __bfloat162float(h));
    }
}

// ---------------- mma.sync bf16-split GEMM ----------------
// CTA 128x128, 8 warps of 64x32 (2x4), 4-stage cp.async pipeline (KC=16),
// 256 threads, 2 CTAs/SM -> 16 warps/SM (4/SMSP) to hide MMA RAW chains.
// Pipeline structure (NSTG=4, cp_wait<2>, 1 sync/chunk) is the protected R13 config.
#define KC       16
#define NCHUNK   (DMOD/KC)           // 64
#define ROWB     48
#define T_TB     (128*ROWB)          // 6144
#define STAGE_B  (4*T_TB)            // 24576: Ah, Al, Bh, Bl
#define NSTG     4
#define GSMEM_SZ (NSTG*STAGE_B)      // 98304 (x2 CTAs = 196608 <= 227KB)

struct GemmJob {
    const __nv_bfloat16 *Ah, *Al, *Bh, *Bl;
    float* C32;
    __nv_bfloat16 *Ch, *Cl;
    const int* vlen;   // non-null => skip token-dead tiles (K/V projections)
    int mode;
    float alpha;
};
struct GemmBatch { GemmJob j[3]; };

__device__ __forceinline__ void issue_chunk(uint32_t sb, int stage,
    const __nv_bfloat16* __restrict__ Ah, const __nv_bfloat16* __restrict__ Al,
    const __nv_bfloat16* __restrict__ Bh, const __nv_bfloat16* __restrict__ Bl,
    int m0, int n0, int k0, int tid)
{
    const uint32_t so = sb + stage*STAGE_B;
    const __nv_bfloat16* srcs[4] = {Ah + (size_t)m0*DMOD + k0, Al + (size_t)m0*DMOD + k0,
                                    Bh + (size_t)n0*DMOD + k0, Bl + (size_t)n0*DMOD + k0};
    const int row = tid >> 1, cg = tid & 1;       // 256 threads: one 16B chunk per tile
    #pragma unroll
    for (int t = 0; t < 4; t++)
        cp_async16(so + t*T_TB + row*ROWB + cg*16, srcs[t] + (size_t)row*DMOD + cg*8);
}

__global__ __launch_bounds__(256, 2)
void gemm_mma_kernel(GemmBatch P)
{
    extern __shared__ char smem[];
    const uint32_t sb = smem_to_u32(smem);
    const int tid = threadIdx.x;
    const int wid = tid >> 5, lane = tid & 31;
    const int n0 = blockIdx.x * 128;
    const int m0 = blockIdx.y * 128;
    const GemmJob& J = P.j[blockIdx.z];

    // Dead-token skip (K/V projections): whole-CTA early return, no inner branching.
    if (J.vlen) {
        const int bb = m0 >> 11, nn0 = m0 & (NSEQ-1);
        const int hh0 = n0 >> 6;
        const int v0 = J.vlen[bb*NH + hh0], v1 = J.vlen[bb*NH + hh0 + 1];
        const int vmax = v0 > v1 ? v0 : v1;
        if (nn0 >= ((vmax + 63) & ~63)) return;
    }

    const __nv_bfloat16 *Ah = J.Ah, *Al = J.Al, *Bh = J.Bh, *Bl = J.Bl;

    const int wm = (wid & 1) * 64;      // 2 warps along m
    const int wn = (wid >> 1) * 32;     // 4 warps along n

    const int a_row = lane & 15;
    const int a_kh  = lane >> 4;
    const int b_row = ((lane >> 4) << 3) + (lane & 7);
    const int b_kh  = (lane >> 3) & 1;

    float acc[4][4][4];                 // 64 accumulator regs
    #pragma unroll
    for (int mi = 0; mi < 4; mi++)
      #pragma unroll
      for (int ni = 0; ni < 4; ni++)
        #pragma unroll
        for (int r = 0; r < 4; r++) acc[mi][ni][r] = 0.f;

    issue_chunk(sb, 0, Ah, Al, Bh, Bl, m0, n0, 0,     tid); cp_commit();
    issue_chunk(sb, 1, Ah, Al, Bh, Bl, m0, n0, KC,    tid); cp_commit();
    issue_chunk(sb, 2, Ah, Al, Bh, Bl, m0, n0, 2*KC,  tid); cp_commit();

    for (int c = 0; c < NCHUNK; c++) {
        cp_wait<2>();
        __syncthreads();
        if (c + 3 < NCHUNK)
            issue_chunk(sb, (c+3) & (NSTG-1), Ah, Al, Bh, Bl, m0, n0, (c+3)*KC, tid);
        cp_commit();

        const uint32_t so = sb + (c & (NSTG-1))*STAGE_B;
        const uint32_t koff = b_kh*16;
        uint32_t bh[2][4], bl[2][4];
        #pragma unroll
        for (int np = 0; np < 2; np++) {
            uint32_t ba = so + 2*T_TB + (wn + np*16 + b_row)*ROWB + koff;
            ldsm_x4(bh[np][0], bh[np][1], bh[np][2], bh[np][3], ba);
            ldsm_x4(bl[np][0], bl[np][1], bl[np][2], bl[np][3], ba + T_TB);
        }
        const uint32_t akoff = a_kh*16;
        #pragma unroll
        for (int mi = 0; mi < 4; mi++) {
            uint32_t aa = so + (wm + mi*16 + a_row)*ROWB + akoff;
            uint32_t ah0, ah1, ah2, ah3, al0, al1, al2, al3;
            ldsm_x4(ah0, ah1, ah2, ah3, aa);
            ldsm_x4(al0, al1, al2, al3, aa + T_TB);
            #pragma unroll
            for (int ni = 0; ni < 4; ni++) {
                const int np = ni >> 1, hf = (ni & 1) * 2;
                mma16816(acc[mi][ni], ah0, ah1, ah2, ah3, bh[np][hf], bh[np][hf+1]);
                mma16816(acc[mi][ni], ah0, ah1, ah2, ah3, bl[np][hf], bl[np][hf+1]);
                mma16816(acc[mi][ni], al0, al1, al2, al3, bh[np][hf], bh[np][hf+1]);
            }
        }
    }

    const int crow = lane >> 2, ccol = (lane & 3) * 2;
    const int mode = J.mode;
    const float alpha = J.alpha;
    #pragma unroll
    for (int mi = 0; mi < 4; mi++) {
      #pragma unroll
      for (int h = 0; h < 2; h++) {
        const int m = m0 + wm + mi*16 + crow + h*8;
        const int bb = m >> 11, nn = m & (NSEQ-1);
        #pragma unroll
        for (int ni = 0; ni < 4; ni++) {
            const int n = n0 + wn + ni*8 + ccol;
            float x0 = acc[mi][ni][h*2+0] * alpha;
            float x1 = acc[mi][ni][h*2+1] * alpha;
            if (mode == 0) {
                float2 v; v.x = x0; v.y = x1;
                *(float2*)(&J.C32[(size_t)m*DMOD + n]) = v;
            } else if (mode == 1) {
                const int hh = n >> 6, dh = n & 63;
                size_t base = (((size_t)(bb*NH + hh))*NSEQ + nn)*DHD + dh;
                uint32_t hp = pack2(x0, x1);
                *(uint32_t*)(J.Ch + base) = hp;
                *(uint32_t*)(J.Cl + base) = res_pack(hp, x0, x1);
            } else {
                const int hh = n >> 6, dh = n & 63;
                size_t base = (((size_t)(bb*NH + hh))*DHD + dh)*NSEQ + nn;
                J.Ch[base]        = __float2bfloat16(x0);
                J.Ch[base + NSEQ] = __float2bfloat16(x1);
                J.Cl[base]        = __float2bfloat16(bf16_res(x0));
                J.Cl[base + NSEQ] = __float2bfloat16(bf16_res(x1));
            }
        }
      }
    }
}

// ---------------- tensor-core flash attention (unchanged from R13/R15) -----
#define AKT   64
#define ATILE 8192
#define ASMEM (8*ATILE)

__device__ __forceinline__ void attn_load_kv(uint32_t sb, int stage,
    const __nv_bfloat16* __restrict__ Kh, const __nv_bfloat16* __restrict__ Kl,
    const __nv_bfloat16* __restrict__ Vh, const __nv_bfloat16* __restrict__ Vl,
    int bh, int k0, int tid)
{
    const __nv_bfloat16* srcs[4] = {
        Kh + ((size_t)bh*NSEQ + k0)*DHD,
        Kl + ((size_t)bh*NSEQ + k0)*DHD,
        Vh + ((size_t)bh*DHD)*NSEQ + k0,
        Vl + ((size_t)bh*DHD)*NSEQ + k0 };
    const int rstr[4] = {DHD, DHD, NSEQ, NSEQ};
    const uint32_t base = sb + stage*(4*ATILE);
    #pragma unroll
    for (int i = 0; i < 16; i++) {
        const int arr = i >> 2;
        const int idx = i*128 + tid;
        const int row = (idx >> 3) & 63;
        const int cg  = idx & 7;
        cp_async16(base + arr*ATILE + SWZ(row*128 + cg*16),
                   srcs[arr] + (size_t)row*rstr[arr] + cg*8);
    }
}

__global__ __launch_bounds__(128, 3)
void attn_mma_kernel(const __nv_bfloat16* __restrict__ Qh, const __nv_bfloat16* __restrict__ Ql,
                     const __nv_bfloat16* __restrict__ Kh, const __nv_bfloat16* __restrict__ Kl,
                     const __nv_bfloat16* __restrict__ Vh, const __nv_bfloat16* __restrict__ Vl,
                     const int* __restrict__ vlen,
                     __nv_bfloat16* __restrict__ Oh, __nv_bfloat16* __restrict__ Ol)
{
    extern __shared__ char smem[];
    const uint32_t sb = smem_to_u32(smem);
    const int tid = threadIdx.x, wid = tid >> 5, lane = tid & 31;
    const int bh = blockIdx.x, qt = blockIdx.y;
    const int vl = vlen[bh];
    const int ntiles = (vl + AKT - 1) / AKT;
    const int wq0 = wid * 16;

    const int crow = lane >> 2, ccol = (lane & 3) * 2;
    const int b_row = ((lane >> 4) << 3) + (lane & 7);
    const int b_kh = (lane >> 3) & 1;

    attn_load_kv(sb, 0, Kh, Kl, Vh, Vl, bh, 0, tid);
    cp_commit();

    uint32_t qfh[4][4], qfl[4][4];
    {
        const __nv_bfloat16* qh = Qh + ((size_t)bh*NSEQ + qt*64 + wq0)*DHD;
        const __nv_bfloat16* ql = Ql + ((size_t)bh*NSEQ + qt*64 + wq0)*DHD;
        #pragma unroll
        for (int ks = 0; ks < 4; ks++) {
            const int col = ks*16 + ccol;
            qfh[ks][0] = *(const uint32_t*)(qh + (size_t)crow*DHD + col);
            qfh[ks][1] = *(const uint32_t*)(qh + (size_t)(crow+8)*DHD + col);
            qfh[ks][2] = *(const uint32_t*)(qh + (size_t)crow*DHD + col + 8);
            qfh[ks][3] = *(const uint32_t*)(qh + (size_t)(crow+8)*DHD + col + 8);
            qfl[ks][0] = *(const uint32_t*)(ql + (size_t)crow*DHD + col);
            qfl[ks][1] = *(const uint32_t*)(ql + (size_t)(crow+8)*DHD + col);
            qfl[ks][2] = *(const uint32_t*)(ql + (size_t)crow*DHD + col + 8);
            qfl[ks][3] = *(const uint32_t*)(ql + (size_t)(crow+8)*DHD + col + 8);
        }
    }

    float o[8][4];
    float m_i[2] = {-1e30f, -1e30f}, l_i[2] = {0.f, 0.f};
    #pragma unroll
    for (int nt = 0; nt < 8; nt++)
        #pragma unroll
        for (int r = 0; r < 4; r++) o[nt][r] = 0.f;

    for (int kt = 0; kt < ntiles; kt++) {
        cp_wait<0>();
        __syncthreads();
        if (kt + 1 < ntiles) {
            attn_load_kv(sb, (kt+1) & 1, Kh, Kl, Vh, Vl, bh, (kt+1)*AKT, tid);
            cp_commit();
        }

        const uint32_t soK = sb + (kt & 1)*(4*ATILE);

        float s[8][4];
        #pragma unroll
        for (int nt = 0; nt < 8; nt++)
            #pragma unroll
            for (int r = 0; r < 4; r++) s[nt][r] = 0.f;

        #pragma unroll
        for (int ks = 0; ks < 4; ks++) {
            const uint32_t koff = ks*32 + b_kh*16;
            #pragma unroll
            for (int np = 0; np < 4; np++) {
                const uint32_t ro = (np*16 + b_row)*128 + koff;
                const uint32_t ka = soK + SWZ(ro);
                uint32_t kfh[4], kfl[4];
                ldsm_x4(kfh[0], kfh[1], kfh[2], kfh[3], ka);
                ldsm_x4(kfl[0], kfl[1], kfl[2], kfl[3], ka + ATILE);
                #pragma unroll
                for (int t = 0; t < 2; t++) {
                    float* sc = s[np*2 + t];
                    mma16816(sc, qfh[ks][0], qfh[ks][1], qfh[ks][2], qfh[ks][3], kfh[t*2], kfh[t*2+1]);
                    mma16816(sc, qfh[ks][0], qfh[ks][1], qfh[ks][2], qfh[ks][3], kfl[t*2], kfl[t*2+1]);
                    mma16816(sc, qfl[ks][0], qfl[ks][1], qfl[ks][2], qfl[ks][3], kfh[t*2], kfh[t*2+1]);
                }
            }
        }

        const int kb = kt * AKT;
        const bool full = (kb + AKT <= vl);
        #pragma unroll
        for (int h = 0; h < 2; h++) {
            if (!full) {
                #pragma unroll
                for (int nt = 0; nt < 8; nt++) {
                    const int c0 = kb + nt*8 + ccol;
                    if (c0     >= vl) s[nt][h*2]   = -1e30f;
                    if (c0 + 1 >= vl) s[nt][h*2+1] = -1e30f;
                }
            }
            float rmax = -1e30f;
            #pragma unroll
            for (int nt = 0; nt < 8; nt++)
                rmax = fmaxf(rmax, fmaxf(s[nt][h*2], s[nt][h*2+1]));
            rmax = fmaxf(rmax, __shfl_xor_sync(0xffffffffu, rmax, 1));
            rmax = fmaxf(rmax, __shfl_xor_sync(0xffffffffu, rmax, 2));
            const float m_new = fmaxf(m_i[h], rmax);
            const float rsc = fexp2(m_i[h] - m_new);
            m_i[h] = m_new;
            float rsum = 0.f;
            #pragma unroll
            for (int nt = 0; nt < 8; nt++) {
                const float p0 = fexp2(s[nt][h*2]   - m_new);
                const float p1 = fexp2(s[nt][h*2+1] - m_new);
                s[nt][h*2]   = p0;
                s[nt][h*2+1] = p1;
                rsum += p0 + p1;
            }
            rsum += __shfl_xor_sync(0xffffffffu, rsum, 1);
            rsum += __shfl_xor_sync(0xffffffffu, rsum, 2);
            l_i[h] = l_i[h]*rsc + rsum;
            #pragma unroll
            for (int nt = 0; nt < 8; nt++) { o[nt][h*2] *= rsc; o[nt][h*2+1] *= rsc; }
        }

        #pragma unroll
        for (int ks = 0; ks < 4; ks++) {
            const int t0 = 2*ks, t1 = 2*ks + 1;
            const uint32_t ph0 = pack2(s[t0][0], s[t0][1]);
            const uint32_t ph1 = pack2(s[t0][2], s[t0][3]);
            const uint32_t ph2 = pack2(s[t1][0], s[t1][1]);
            const uint32_t ph3 = pack2(s[t1][2], s[t1][3]);
            const uint32_t pl0 = res_pack(ph0, s[t0][0], s[t0][1]);
            const uint32_t pl1 = res_pack(ph1, s[t0][2], s[t0][3]);
            const uint32_t pl2 = res_pack(ph2, s[t1][0], s[t1][1]);
            const uint32_t pl3 = res_pack(ph3, s[t1][2], s[t1][3]);
            const uint32_t koff = ks*32 + b_kh*16;
            #pragma unroll
            for (int np = 0; np < 4; np++) {
                const uint32_t ro = (np*16 + b_row)*128 + koff;
                const uint32_t va = soK + 2*ATILE + SWZ(ro);
                uint32_t vfh[4], vfl[4];
                ldsm_x4(vfh[0], vfh[1], vfh[2], vfh[3], va);
                ldsm_x4(vfl[0], vfl[1], vfl[2], vfl[3], va + ATILE);
                #pragma unroll
                for (int t = 0; t < 2; t++) {
                    float* oc = o[np*2 + t];
                    mma16816(oc, ph0, ph1, ph2, ph3, vfh[t*2], vfh[t*2+1]);
                    mma16816(oc, ph0, ph1, ph2, ph3, vfl[t*2], vfl[t*2+1]);
                    mma16816(oc, pl0, pl1, pl2, pl3, vfh[t*2], vfh[t*2+1]);
                }
            }
        }
    }

    const int bb = bh >> 4, hh = bh & 15;
    #pragma unroll
    for (int h = 0; h < 2; h++) {
        const float inv = 1.0f / l_i[h];
        const int ntok = qt*64 + wq0 + crow + h*8;
        const size_t base = ((size_t)(bb*NSEQ) + ntok)*DMOD + hh*64 + ccol;
        #pragma unroll
        for (int nt = 0; nt < 8; nt++) {
            const float x0 = o[nt][h*2]   * inv;
            const float x1 = o[nt][h*2+1] * inv;
            uint32_t hp = pack2(x0, x1);
            *(uint32_t*)(Oh + base + nt*8) = hp;
            *(uint32_t*)(Ol + base + nt*8) = res_pack(hp, x0, x1);
        }
    }
}

// ---------------------------------------------------------------------------
extern "C" void kernel_launch(void* const* d_in, const int* in_sizes, int n_in,
                              void* d_out, int out_size) {
    const float* queries = (const float*)d_in[0];
    const float* keys    = (const float*)d_in[1];
    const float* values  = (const float*)d_in[2];
    const int*   vlen    = (const int*)  d_in[3];
    const float* Wq      = (const float*)d_in[4];
    const float* Wk      = (const float*)d_in[5];
    const float* Wv      = (const float*)d_in[6];
    const float* Wo      = (const float*)d_in[7];
    float* out = (float*)d_out;

    __nv_bfloat16 *pAh, *pAl, *pWth, *pWtl, *pQh, *pQl, *pKh, *pKl, *pVh, *pVl;
    cudaGetSymbolAddress((void**)&pAh,  g_Ah);
    cudaGetSymbolAddress((void**)&pAl,  g_Al);
    cudaGetSymbolAddress((void**)&pWth, g_Wth);
    cudaGetSymbolAddress((void**)&pWtl, g_Wtl);
    cudaGetSymbolAddress((void**)&pQh,  g_Qh);
    cudaGetSymbolAddress((void**)&pQl,  g_Ql);
    cudaGetSymbolAddress((void**)&pKh,  g_Kh);
    cudaGetSymbolAddress((void**)&pKl,  g_Kl);
    cudaGetSymbolAddress((void**)&pVh,  g_Vth);
    cudaGetSymbolAddress((void**)&pVl,  g_Vtl);

    cudaFuncSetAttribute(gemm_mma_kernel, cudaFuncAttributeMaxDynamicSharedMemorySize, GSMEM_SZ);
    cudaFuncSetAttribute(attn_mma_kernel, cudaFuncAttributeMaxDynamicSharedMemorySize, ASMEM);

    const int n4 = MROWS*DMOD/4;
    const size_t AD = (size_t)MROWS*DMOD;

    wsplit_all<<<dim3(DMOD/32, DMOD/32, 4), dim3(32, 8)>>>(Wq, Wk, Wv, Wo, pWth, pWtl);
    asplit_all<<<dim3(n4/256, 1, 3), 256>>>((const float4*)queries, (const float4*)keys,
                                            (const float4*)values, (uint2*)pAh, (uint2*)pAl, n4);

    GemmBatch qkv;
    qkv.j[0] = { pAh,        pAl,        pWth,        pWtl,        nullptr, pQh, pQl, nullptr, 1, 0.18033688f };
    qkv.j[1] = { pAh + AD,   pAl + AD,   pWth + DD,   pWtl + DD,   nullptr, pKh, pKl, vlen,    1, 1.0f };
    qkv.j[2] = { pAh + 2*AD, pAl + 2*AD, pWth + 2*DD, pWtl + 2*DD, nullptr, pVh, pVl, vlen,    2, 1.0f };
    gemm_mma_kernel<<<dim3(DMOD/128, MROWS/128, 3), 256, GSMEM_SZ>>>(qkv);

    attn_mma_kernel<<<dim3(BSZ*NH, NSEQ/64), 128, ASMEM>>>(pQh, pQl, pKh, pKl, pVh, pVl,
                                                           vlen, pAh, pAl);

    GemmBatch ob;
    ob.j[0] = { pAh, pAl, pWth + 3*DD, pWtl + 3*DD, out, nullptr, nullptr, nullptr, 0, 1.0f };
    ob.j[1] = ob.j[0]; ob.j[2] = ob.j[0];
    gemm_mma_kernel<<<dim3(DMOD/128, MROWS/128, 1), 256, GSMEM_SZ>>>(ob);
}

// round 17
// speedup vs baseline: 1.0160x; 1.0160x over previous
#include <cuda_runtime.h>
#include <cuda_bf16.h>
#include <cstdint>

#define BSZ   2
#define NSEQ  2048
#define DMOD  1024
#define NH    16
#define DHD   64
#define MROWS (BSZ*NSEQ)
#define DD    (DMOD*DMOD)

// ---------------- device scratch (no allocations allowed) ----------------
__device__ __nv_bfloat16 g_Ah[3*MROWS*DMOD];
__device__ __nv_bfloat16 g_Al[3*MROWS*DMOD];
__device__ __nv_bfloat16 g_Wth[4*DD];
__device__ __nv_bfloat16 g_Wtl[4*DD];
__device__ __nv_bfloat16 g_Qh[MROWS*DMOD];     // [bh][n][dh], pre-scaled by 0.125*log2e
__device__ __nv_bfloat16 g_Ql[MROWS*DMOD];
__device__ __nv_bfloat16 g_Kh[MROWS*DMOD];     // [bh][n][dh]
__device__ __nv_bfloat16 g_Kl[MROWS*DMOD];
__device__ __nv_bfloat16 g_Vth[MROWS*DMOD];    // [bh][dh][n]
__device__ __nv_bfloat16 g_Vtl[MROWS*DMOD];

// ---------------- PTX helpers ----------------
__device__ __forceinline__ uint32_t smem_to_u32(const void* p) {
    uint32_t a;
    asm("{ .reg .u64 t; cvta.to.shared.u64 t, %1; cvt.u32.u64 %0, t; }" : "=r"(a) : "l"(p));
    return a;
}
__device__ __forceinline__ void cp_async16(uint32_t dst, const void* src) {
    asm volatile("cp.async.cg.shared.global [%0], [%1], 16;" :: "r"(dst), "l"(src));
}
__device__ __forceinline__ void cp_commit() {
    asm volatile("cp.async.commit_group;" ::: "memory");
}
template <int N>
__device__ __forceinline__ void cp_wait() {
    asm volatile("cp.async.wait_group %0;" :: "n"(N) : "memory");
}
__device__ __forceinline__ void ldsm_x4(uint32_t& r0, uint32_t& r1, uint32_t& r2,
                                        uint32_t& r3, uint32_t addr) {
    asm volatile("ldmatrix.sync.aligned.m8n8.x4.shared.b16 {%0,%1,%2,%3}, [%4];"
                 : "=r"(r0), "=r"(r1), "=r"(r2), "=r"(r3) : "r"(addr));
}
__device__ __forceinline__ void mma16816(float* c, uint32_t a0, uint32_t a1,
                                         uint32_t a2, uint32_t a3,
                                         uint32_t b0, uint32_t b1) {
    asm volatile("mma.sync.aligned.m16n8k16.row.col.f32.bf16.bf16.f32 "
                 "{%0,%1,%2,%3}, {%4,%5,%6,%7}, {%8,%9}, {%0,%1,%2,%3};"
                 : "+f"(c[0]), "+f"(c[1]), "+f"(c[2]), "+f"(c[3])
                 : "r"(a0), "r"(a1), "r"(a2), "r"(a3), "r"(b0), "r"(b1));
}

// exp2 via SFU: single instruction, rel err ~2^-22, ex2(-huge) = 0 exactly.
__device__ __forceinline__ float fexp2(float t) {
    float r;
    asm("ex2.approx.f32 %0, %1;" : "=f"(r) : "f"(t));
    return r;
}

__device__ __forceinline__ uint32_t pack2(float a, float b) {
    uint32_t r;
    asm("cvt.rn.bf16x2.f32 %0, %1, %2;" : "=r"(r) : "f"(b), "f"(a));
    return r;
}
__device__ __forceinline__ uint32_t res_pack(uint32_t hpk, float a, float b) {
    float ha = __int_as_float(hpk << 16);
    float hb = __int_as_float(hpk & 0xffff0000u);
    return pack2(a - ha, b - hb);
}
__device__ __forceinline__ float bf16_res(float x) {
    return x - __bfloat162float(__float2bfloat16(x));
}
#define SWZ(o) ((o) ^ (((o) >> 3) & 0x70))

// ---------------- prep kernels ----------------
__global__ __launch_bounds__(256)
void asplit_all(const float4* __restrict__ X0, const float4* __restrict__ X1,
                const float4* __restrict__ X2, uint2* __restrict__ Xh,
                uint2* __restrict__ Xl, int n4)
{
    const int z = blockIdx.z;
    const float4* X = (z == 0) ? X0 : ((z == 1) ? X1 : X2);
    int i = blockIdx.x*256 + threadIdx.x;
    if (i >= n4) return;
    float4 v = X[i];
    uint2 uh, ul;
    uh.x = pack2(v.x, v.y); uh.y = pack2(v.z, v.w);
    ul.x = res_pack(uh.x, v.x, v.y); ul.y = res_pack(uh.y, v.z, v.w);
    Xh[(size_t)z*n4 + i] = uh; Xl[(size_t)z*n4 + i] = ul;
}

__global__ __launch_bounds__(256)
void wsplit_all(const float* __restrict__ W0, const float* __restrict__ W1,
                const float* __restrict__ W2, const float* __restrict__ W3,
                __nv_bfloat16* __restrict__ Wth, __nv_bfloat16* __restrict__ Wtl)
{
    __shared__ float ts[32][33];
    const int z = blockIdx.z;
    const float* W = (z == 0) ? W0 : ((z == 1) ? W1 : ((z == 2) ? W2 : W3));
    __nv_bfloat16* th = Wth + (size_t)z*DD;
    __nv_bfloat16* tl = Wtl + (size_t)z*DD;
    const int tx = threadIdx.x, ty = threadIdx.y;
    const int gx = blockIdx.x*32, gy = blockIdx.y*32;
    #pragma unroll
    for (int i = ty; i < 32; i += 8)
        ts[i][tx] = W[(size_t)(gy+i)*DMOD + gx + tx];
    __syncthreads();
    #pragma unroll
    for (int i = ty; i < 32; i += 8) {
        float v = ts[tx][i];
        __nv_bfloat16 h = __float2bfloat16(v);
        th[(size_t)(gx+i)*DMOD + gy + tx] = h;
        tl[(size_t)(gx+i)*DMOD + gy + tx] = __float2bfloat16(v - __bfloat162float(h));
    }
}

// ---------------- mma.sync bf16-split GEMM (protected R13 config) ----------
// CTA 128x128, 4 warps of 64x64, 4-stage cp.async pipeline (KC=16), 2 CTAs/SM.
#define KC       16
#define NCHUNK   (DMOD/KC)           // 64
#define ROWB     48
#define T_TB     (128*ROWB)          // 6144
#define STAGE_B  (4*T_TB)            // 24576: Ah, Al, Bh, Bl
#define NSTG     4
#define GSMEM_SZ (NSTG*STAGE_B)      // 98304

struct GemmJob {
    const __nv_bfloat16 *Ah, *Al, *Bh, *Bl;
    float* C32;
    __nv_bfloat16 *Ch, *Cl;
    const int* vlen;   // non-null => skip token-dead tiles (K/V projections)
    int mode;
    float alpha;
};
struct GemmBatch { GemmJob j[3]; };

__device__ __forceinline__ void issue_chunk(uint32_t sb, int stage,
    const __nv_bfloat16* __restrict__ Ah, const __nv_bfloat16* __restrict__ Al,
    const __nv_bfloat16* __restrict__ Bh, const __nv_bfloat16* __restrict__ Bl,
    int m0, int n0, int k0, int tid)
{
    const uint32_t so = sb + stage*STAGE_B;
    const __nv_bfloat16* srcs[4] = {Ah + (size_t)m0*DMOD + k0, Al + (size_t)m0*DMOD + k0,
                                    Bh + (size_t)n0*DMOD + k0, Bl + (size_t)n0*DMOD + k0};
    #pragma unroll
    for (int t = 0; t < 4; t++) {
        #pragma unroll
        for (int i = 0; i < 2; i++) {
            int idx = i*128 + tid;          // 0..255
            int row = idx >> 1, cg = idx & 1;
            cp_async16(so + t*T_TB + row*ROWB + cg*16, srcs[t] + (size_t)row*DMOD + cg*8);
        }
    }
}

__global__ __launch_bounds__(128, 2)
void gemm_mma_kernel(GemmBatch P)
{
    extern __shared__ char smem[];
    const uint32_t sb = smem_to_u32(smem);
    const int tid = threadIdx.x;
    const int wid = tid >> 5, lane = tid & 31;
    const int n0 = blockIdx.x * 128;
    const int m0 = blockIdx.y * 128;
    const GemmJob& J = P.j[blockIdx.z];

    // Dead-token skip (K/V projections): whole-CTA early return, no inner branching.
    if (J.vlen) {
        const int bb = m0 >> 11, nn0 = m0 & (NSEQ-1);
        const int hh0 = n0 >> 6;
        const int v0 = J.vlen[bb*NH + hh0], v1 = J.vlen[bb*NH + hh0 + 1];
        const int vmax = v0 > v1 ? v0 : v1;
        if (nn0 >= ((vmax + 63) & ~63)) return;
    }

    const __nv_bfloat16 *Ah = J.Ah, *Al = J.Al, *Bh = J.Bh, *Bl = J.Bl;

    const int wm = (wid & 1) * 64;
    const int wn = (wid >> 1) * 64;

    const int a_row = lane & 15;
    const int a_kh  = lane >> 4;
    const int b_row = ((lane >> 4) << 3) + (lane & 7);
    const int b_kh  = (lane >> 3) & 1;

    float acc[4][8][4];
    #pragma unroll
    for (int mi = 0; mi < 4; mi++)
      #pragma unroll
      for (int ni = 0; ni < 8; ni++)
        #pragma unroll
        for (int r = 0; r < 4; r++) acc[mi][ni][r] = 0.f;

    issue_chunk(sb, 0, Ah, Al, Bh, Bl, m0, n0, 0,     tid); cp_commit();
    issue_chunk(sb, 1, Ah, Al, Bh, Bl, m0, n0, KC,    tid); cp_commit();
    issue_chunk(sb, 2, Ah, Al, Bh, Bl, m0, n0, 2*KC,  tid); cp_commit();

    for (int c = 0; c < NCHUNK; c++) {
        cp_wait<2>();
        __syncthreads();
        if (c + 3 < NCHUNK)
            issue_chunk(sb, (c+3) & (NSTG-1), Ah, Al, Bh, Bl, m0, n0, (c+3)*KC, tid);
        cp_commit();

        const uint32_t so = sb + (c & (NSTG-1))*STAGE_B;
        const uint32_t koff = b_kh*16;
        uint32_t bh[4][4], bl[4][4];
        #pragma unroll
        for (int np = 0; np < 4; np++) {
            uint32_t ba = so + 2*T_TB + (wn + np*16 + b_row)*ROWB + koff;
            ldsm_x4(bh[np][0], bh[np][1], bh[np][2], bh[np][3], ba);
            ldsm_x4(bl[np][0], bl[np][1], bl[np][2], bl[np][3], ba + T_TB);
        }
        const uint32_t akoff = a_kh*16;
        #pragma unroll
        for (int mi = 0; mi < 4; mi++) {
            uint32_t aa = so + (wm + mi*16 + a_row)*ROWB + akoff;
            uint32_t ah0, ah1, ah2, ah3, al0, al1, al2, al3;
            ldsm_x4(ah0, ah1, ah2, ah3, aa);
            ldsm_x4(al0, al1, al2, al3, aa + T_TB);
            #pragma unroll
            for (int ni = 0; ni < 8; ni++) {
                const int np = ni >> 1, hf = (ni & 1) * 2;
                mma16816(acc[mi][ni], ah0, ah1, ah2, ah3, bh[np][hf], bh[np][hf+1]);
                mma16816(acc[mi][ni], ah0, ah1, ah2, ah3, bl[np][hf], bl[np][hf+1]);
                mma16816(acc[mi][ni], al0, al1, al2, al3, bh[np][hf], bh[np][hf+1]);
            }
        }
    }

    const int crow = lane >> 2, ccol = (lane & 3) * 2;
    const int mode = J.mode;
    const float alpha = J.alpha;
    #pragma unroll
    for (int mi = 0; mi < 4; mi++) {
      #pragma unroll
      for (int h = 0; h < 2; h++) {
        const int m = m0 + wm + mi*16 + crow + h*8;
        const int bb = m >> 11, nn = m & (NSEQ-1);
        #pragma unroll
        for (int ni = 0; ni < 8; ni++) {
            const int n = n0 + wn + ni*8 + ccol;
            float x0 = acc[mi][ni][h*2+0] * alpha;
            float x1 = acc[mi][ni][h*2+1] * alpha;
            if (mode == 0) {
                float2 v; v.x = x0; v.y = x1;
                *(float2*)(&J.C32[(size_t)m*DMOD + n]) = v;
            } else if (mode == 1) {
                const int hh = n >> 6, dh = n & 63;
                size_t base = (((size_t)(bb*NH + hh))*NSEQ + nn)*DHD + dh;
                uint32_t hp = pack2(x0, x1);
                *(uint32_t*)(J.Ch + base) = hp;
                *(uint32_t*)(J.Cl + base) = res_pack(hp, x0, x1);
            } else {
                const int hh = n >> 6, dh = n & 63;
                size_t base = (((size_t)(bb*NH + hh))*DHD + dh)*NSEQ + nn;
                J.Ch[base]        = __float2bfloat16(x0);
                J.Ch[base + NSEQ] = __float2bfloat16(x1);
                J.Cl[base]        = __float2bfloat16(bf16_res(x0));
                J.Cl[base + NSEQ] = __float2bfloat16(bf16_res(x1));
            }
        }
      }
    }
}

// ---------------- tensor-core flash attention ----------------
// R13 base; softmax h-halves manually interleaved to halve the serial
// shfl->ex2->shfl dependency chain per k-tile.
#define AKT   64
#define ATILE 8192
#define ASMEM (8*ATILE)

__device__ __forceinline__ void attn_load_kv(uint32_t sb, int stage,
    const __nv_bfloat16* __restrict__ Kh, const __nv_bfloat16* __restrict__ Kl,
    const __nv_bfloat16* __restrict__ Vh, const __nv_bfloat16* __restrict__ Vl,
    int bh, int k0, int tid)
{
    const __nv_bfloat16* srcs[4] = {
        Kh + ((size_t)bh*NSEQ + k0)*DHD,
        Kl + ((size_t)bh*NSEQ + k0)*DHD,
        Vh + ((size_t)bh*DHD)*NSEQ + k0,
        Vl + ((size_t)bh*DHD)*NSEQ + k0 };
    const int rstr[4] = {DHD, DHD, NSEQ, NSEQ};
    const uint32_t base = sb + stage*(4*ATILE);
    #pragma unroll
    for (int i = 0; i < 16; i++) {
        const int arr = i >> 2;
        const int idx = i*128 + tid;
        const int row = (idx >> 3) & 63;
        const int cg  = idx & 7;
        cp_async16(base + arr*ATILE + SWZ(row*128 + cg*16),
                   srcs[arr] + (size_t)row*rstr[arr] + cg*8);
    }
}

__global__ __launch_bounds__(128, 3)
void attn_mma_kernel(const __nv_bfloat16* __restrict__ Qh, const __nv_bfloat16* __restrict__ Ql,
                     const __nv_bfloat16* __restrict__ Kh, const __nv_bfloat16* __restrict__ Kl,
                     const __nv_bfloat16* __restrict__ Vh, const __nv_bfloat16* __restrict__ Vl,
                     const int* __restrict__ vlen,
                     __nv_bfloat16* __restrict__ Oh, __nv_bfloat16* __restrict__ Ol)
{
    extern __shared__ char smem[];
    const uint32_t sb = smem_to_u32(smem);
    const int tid = threadIdx.x, wid = tid >> 5, lane = tid & 31;
    const int bh = blockIdx.x, qt = blockIdx.y;
    const int vl = vlen[bh];
    const int ntiles = (vl + AKT - 1) / AKT;
    const int wq0 = wid * 16;

    const int crow = lane >> 2, ccol = (lane & 3) * 2;
    const int b_row = ((lane >> 4) << 3) + (lane & 7);
    const int b_kh = (lane >> 3) & 1;

    attn_load_kv(sb, 0, Kh, Kl, Vh, Vl, bh, 0, tid);
    cp_commit();

    uint32_t qfh[4][4], qfl[4][4];
    {
        const __nv_bfloat16* qh = Qh + ((size_t)bh*NSEQ + qt*64 + wq0)*DHD;
        const __nv_bfloat16* ql = Ql + ((size_t)bh*NSEQ + qt*64 + wq0)*DHD;
        #pragma unroll
        for (int ks = 0; ks < 4; ks++) {
            const int col = ks*16 + ccol;
            qfh[ks][0] = *(const uint32_t*)(qh + (size_t)crow*DHD + col);
            qfh[ks][1] = *(const uint32_t*)(qh + (size_t)(crow+8)*DHD + col);
            qfh[ks][2] = *(const uint32_t*)(qh + (size_t)crow*DHD + col + 8);
            qfh[ks][3] = *(const uint32_t*)(qh + (size_t)(crow+8)*DHD + col + 8);
            qfl[ks][0] = *(const uint32_t*)(ql + (size_t)crow*DHD + col);
            qfl[ks][1] = *(const uint32_t*)(ql + (size_t)(crow+8)*DHD + col);
            qfl[ks][2] = *(const uint32_t*)(ql + (size_t)crow*DHD + col + 8);
            qfl[ks][3] = *(const uint32_t*)(ql + (size_t)(crow+8)*DHD + col + 8);
        }
    }

    float o[8][4];
    float m_i[2] = {-1e30f, -1e30f}, l_i[2] = {0.f, 0.f};
    #pragma unroll
    for (int nt = 0; nt < 8; nt++)
        #pragma unroll
        for (int r = 0; r < 4; r++) o[nt][r] = 0.f;

    for (int kt = 0; kt < ntiles; kt++) {
        cp_wait<0>();
        __syncthreads();
        if (kt + 1 < ntiles) {
            attn_load_kv(sb, (kt+1) & 1, Kh, Kl, Vh, Vl, bh, (kt+1)*AKT, tid);
            cp_commit();
        }

        const uint32_t soK = sb + (kt & 1)*(4*ATILE);

        float s[8][4];
        #pragma unroll
        for (int nt = 0; nt < 8; nt++)
            #pragma unroll
            for (int r = 0; r < 4; r++) s[nt][r] = 0.f;

        #pragma unroll
        for (int ks = 0; ks < 4; ks++) {
            const uint32_t koff = ks*32 + b_kh*16;
            #pragma unroll
            for (int np = 0; np < 4; np++) {
                const uint32_t ro = (np*16 + b_row)*128 + koff;
                const uint32_t ka = soK + SWZ(ro);
                uint32_t kfh[4], kfl[4];
                ldsm_x4(kfh[0], kfh[1], kfh[2], kfh[3], ka);
                ldsm_x4(kfl[0], kfl[1], kfl[2], kfl[3], ka + ATILE);
                #pragma unroll
                for (int t = 0; t < 2; t++) {
                    float* sc = s[np*2 + t];
                    mma16816(sc, qfh[ks][0], qfh[ks][1], qfh[ks][2], qfh[ks][3], kfh[t*2], kfh[t*2+1]);
                    mma16816(sc, qfh[ks][0], qfh[ks][1], qfh[ks][2], qfh[ks][3], kfl[t*2], kfl[t*2+1]);
                    mma16816(sc, qfl[ks][0], qfl[ks][1], qfl[ks][2], qfl[ks][3], kfh[t*2], kfh[t*2+1]);
                }
            }
        }

        // ---- masking + online softmax, both h-halves interleaved ----
        const int kb = kt * AKT;
        const bool full = (kb + AKT <= vl);
        if (!full) {
            #pragma unroll
            for (int nt = 0; nt < 8; nt++) {
                const int c0 = kb + nt*8 + ccol;
                if (c0     >= vl) { s[nt][0] = -1e30f; s[nt][2] = -1e30f; }
                if (c0 + 1 >= vl) { s[nt][1] = -1e30f; s[nt][3] = -1e30f; }
            }
        }
        // phase 1: both row-max reductions (independent shfl chains, pipelined)
        float rmax0 = -1e30f, rmax1 = -1e30f;
        #pragma unroll
        for (int nt = 0; nt < 8; nt++) {
            rmax0 = fmaxf(rmax0, fmaxf(s[nt][0], s[nt][1]));
            rmax1 = fmaxf(rmax1, fmaxf(s[nt][2], s[nt][3]));
        }
        rmax0 = fmaxf(rmax0, __shfl_xor_sync(0xffffffffu, rmax0, 1));
        rmax1 = fmaxf(rmax1, __shfl_xor_sync(0xffffffffu, rmax1, 1));
        rmax0 = fmaxf(rmax0, __shfl_xor_sync(0xffffffffu, rmax0, 2));
        rmax1 = fmaxf(rmax1, __shfl_xor_sync(0xffffffffu, rmax1, 2));
        const float mn0 = fmaxf(m_i[0], rmax0);
        const float mn1 = fmaxf(m_i[1], rmax1);
        const float rsc0 = fexp2(m_i[0] - mn0);
        const float rsc1 = fexp2(m_i[1] - mn1);
        m_i[0] = mn0; m_i[1] = mn1;
        // phase 2: all exps (both halves feed the MUFU pipe back-to-back)
        float rsum0 = 0.f, rsum1 = 0.f;
        #pragma unroll
        for (int nt = 0; nt < 8; nt++) {
            const float p0 = fexp2(s[nt][0] - mn0);
            const float p1 = fexp2(s[nt][1] - mn0);
            const float p2 = fexp2(s[nt][2] - mn1);
            const float p3 = fexp2(s[nt][3] - mn1);
            s[nt][0] = p0; s[nt][1] = p1; s[nt][2] = p2; s[nt][3] = p3;
            rsum0 += p0 + p1;
            rsum1 += p2 + p3;
        }
        // phase 3: both sum reductions (pipelined shfls)
        rsum0 += __shfl_xor_sync(0xffffffffu, rsum0, 1);
        rsum1 += __shfl_xor_sync(0xffffffffu, rsum1, 1);
        rsum0 += __shfl_xor_sync(0xffffffffu, rsum0, 2);
        rsum1 += __shfl_xor_sync(0xffffffffu, rsum1, 2);
        l_i[0] = l_i[0]*rsc0 + rsum0;
        l_i[1] = l_i[1]*rsc1 + rsum1;
        // phase 4: rescale accumulators (both halves)
        #pragma unroll
        for (int nt = 0; nt < 8; nt++) {
            o[nt][0] *= rsc0; o[nt][1] *= rsc0;
            o[nt][2] *= rsc1; o[nt][3] *= rsc1;
        }

        // ---- O += P . V with register-built P fragments ----
        #pragma unroll
        for (int ks = 0; ks < 4; ks++) {
            const int t0 = 2*ks, t1 = 2*ks + 1;
            const uint32_t ph0 = pack2(s[t0][0], s[t0][1]);
            const uint32_t ph1 = pack2(s[t0][2], s[t0][3]);
            const uint32_t ph2 = pack2(s[t1][0], s[t1][1]);
            const uint32_t ph3 = pack2(s[t1][2], s[t1][3]);
            const uint32_t pl0 = res_pack(ph0, s[t0][0], s[t0][1]);
            const uint32_t pl1 = res_pack(ph1, s[t0][2], s[t0][3]);
            const uint32_t pl2 = res_pack(ph2, s[t1][0], s[t1][1]);
            const uint32_t pl3 = res_pack(ph3, s[t1][2], s[t1][3]);
            const uint32_t koff = ks*32 + b_kh*16;
            #pragma unroll
            for (int np = 0; np < 4; np++) {
                const uint32_t ro = (np*16 + b_row)*128 + koff;
                const uint32_t va = soK + 2*ATILE + SWZ(ro);
                uint32_t vfh[4], vfl[4];
                ldsm_x4(vfh[0], vfh[1], vfh[2], vfh[3], va);
                ldsm_x4(vfl[0], vfl[1], vfl[2], vfl[3], va + ATILE);
                #pragma unroll
                for (int t = 0; t < 2; t++) {
                    float* oc = o[np*2 + t];
                    mma16816(oc, ph0, ph1, ph2, ph3, vfh[t*2], vfh[t*2+1]);
                    mma16816(oc, ph0, ph1, ph2, ph3, vfl[t*2], vfl[t*2+1]);
                    mma16816(oc, pl0, pl1, pl2, pl3, vfh[t*2], vfh[t*2+1]);
                }
            }
        }
    }

    const int bb = bh >> 4, hh = bh & 15;
    #pragma unroll
    for (int h = 0; h < 2; h++) {
        const float inv = 1.0f / l_i[h];
        const int ntok = qt*64 + wq0 + crow + h*8;
        const size_t base = ((size_t)(bb*NSEQ) + ntok)*DMOD + hh*64 + ccol;
        #pragma unroll
        for (int nt = 0; nt < 8; nt++) {
            const float x0 = o[nt][h*2]   * inv;
            const float x1 = o[nt][h*2+1] * inv;
            uint32_t hp = pack2(x0, x1);
            *(uint32_t*)(Oh + base + nt*8) = hp;
            *(uint32_t*)(Ol + base + nt*8) = res_pack(hp, x0, x1);
        }
    }
}

// ---------------------------------------------------------------------------
extern "C" void kernel_launch(void* const* d_in, const int* in_sizes, int n_in,
                              void* d_out, int out_size) {
    const float* queries = (const float*)d_in[0];
    const float* keys    = (const float*)d_in[1];
    const float* values  = (const float*)d_in[2];
    const int*   vlen    = (const int*)  d_in[3];
    const float* Wq      = (const float*)d_in[4];
    const float* Wk      = (const float*)d_in[5];
    const float* Wv      = (const float*)d_in[6];
    const float* Wo      = (const float*)d_in[7];
    float* out = (float*)d_out;

    __nv_bfloat16 *pAh, *pAl, *pWth, *pWtl, *pQh, *pQl, *pKh, *pKl, *pVh, *pVl;
    cudaGetSymbolAddress((void**)&pAh,  g_Ah);
    cudaGetSymbolAddress((void**)&pAl,  g_Al);
    cudaGetSymbolAddress((void**)&pWth, g_Wth);
    cudaGetSymbolAddress((void**)&pWtl, g_Wtl);
    cudaGetSymbolAddress((void**)&pQh,  g_Qh);
    cudaGetSymbolAddress((void**)&pQl,  g_Ql);
    cudaGetSymbolAddress((void**)&pKh,  g_Kh);
    cudaGetSymbolAddress((void**)&pKl,  g_Kl);
    cudaGetSymbolAddress((void**)&pVh,  g_Vth);
    cudaGetSymbolAddress((void**)&pVl,  g_Vtl);

    cudaFuncSetAttribute(gemm_mma_kernel, cudaFuncAttributeMaxDynamicSharedMemorySize, GSMEM_SZ);
    cudaFuncSetAttribute(attn_mma_kernel, cudaFuncAttributeMaxDynamicSharedMemorySize, ASMEM);

    const int n4 = MROWS*DMOD/4;
    const size_t AD = (size_t)MROWS*DMOD;

    wsplit_all<<<dim3(DMOD/32, DMOD/32, 4), dim3(32, 8)>>>(Wq, Wk, Wv, Wo, pWth, pWtl);
    asplit_all<<<dim3(n4/256, 1, 3), 256>>>((const float4*)queries, (const float4*)keys,
                                            (const float4*)values, (uint2*)pAh, (uint2*)pAl, n4);

    GemmBatch qkv;
    qkv.j[0] = { pAh,        pAl,        pWth,        pWtl,        nullptr, pQh, pQl, nullptr, 1, 0.18033688f };
    qkv.j[1] = { pAh + AD,   pAl + AD,   pWth + DD,   pWtl + DD,   nullptr, pKh, pKl, vlen,    1, 1.0f };
    qkv.j[2] = { pAh + 2*AD, pAl + 2*AD, pWth + 2*DD, pWtl + 2*DD, nullptr, pVh, pVl, vlen,    2, 1.0f };
    gemm_mma_kernel<<<dim3(DMOD/128, MROWS/128, 3), 128, GSMEM_SZ>>>(qkv);

    attn_mma_kernel<<<dim3(BSZ*NH, NSEQ/64), 128, ASMEM>>>(pQh, pQl, pKh, pKl, pVh, pVl,
                                                           vlen, pAh, pAl);

    GemmBatch ob;
    ob.j[0] = { pAh, pAl, pWth + 3*DD, pWtl + 3*DD, out, nullptr, nullptr, nullptr, 0, 1.0f };
    ob.j[1] = ob.j[0]; ob.j[2] = ob.j[0];
    gemm_mma_kernel<<<dim3(DMOD/128, MROWS/128, 1), 128, GSMEM_SZ>>>(ob);
}